// round 1
// baseline (speedup 1.0000x reference)
#include <cuda_runtime.h>
#include <cuda_bf16.h>
#include <math.h>

// Problem constants (fixed by the dataset)
#define MAXN 50000
#define MAXE 800000
#define F128 128

// ---------------- scratch (device globals; no allocation allowed) ----------
__device__ float g_hs[MAXN * F128];    // hs buffer (layer1 then layer2, reused)
__device__ float g_acc[MAXN * F128];   // acc buffer (agg1 then agg2, reused)
__device__ float g_dinv[MAXN];
__device__ int   g_indeg[MAXN];
__device__ int   g_off[MAXN];
__device__ int   g_cur[MAXN];
__device__ int   g_csr[MAXE];
__device__ float g_Wc[F128 * F128];    // Wl @ W2
__device__ float g_bpre[F128];         // bl @ W2
__device__ int   g_bsum[256];
__device__ int   g_bex[256];

// ---------------- helpers ----------------
__device__ __forceinline__ float4 f4add(float4 a, float4 b) {
    return make_float4(a.x + b.x, a.y + b.y, a.z + b.z, a.w + b.w);
}

__device__ __forceinline__ void atomicMaxFloat(float* addr, float v) {
    if (v >= 0.0f) atomicMax((int*)addr, __float_as_int(v));
    else           atomicMin((unsigned int*)addr, __float_as_uint(v));
}

// ---------------- preprocessing ----------------
__global__ void k_init_indeg(int N) {
    int n = blockIdx.x * blockDim.x + threadIdx.x;
    if (n < N) g_indeg[n] = 0;
}

__global__ void k_count(const int* __restrict__ ei, int E) {
    int e = blockIdx.x * blockDim.x + threadIdx.x;
    if (e < E) atomicAdd(&g_indeg[ei[E + e]], 1);
}

__global__ void k_dinv(int N) {
    int n = blockIdx.x * blockDim.x + threadIdx.x;
    if (n < N) g_dinv[n] = rsqrtf((float)(g_indeg[n] + 1));  // +1 self loop
}

__global__ void k_scan_p1(int N) {
    __shared__ int sm[256];
    int t = threadIdx.x;
    int n = blockIdx.x * 256 + t;
    sm[t] = (n < N) ? g_indeg[n] : 0;
    __syncthreads();
    for (int s = 128; s > 0; s >>= 1) {
        if (t < s) sm[t] += sm[t + s];
        __syncthreads();
    }
    if (t == 0) g_bsum[blockIdx.x] = sm[0];
}

__global__ void k_scan_p2(int NB) {
    __shared__ int sm[256];
    int t = threadIdx.x;
    int v = (t < NB) ? g_bsum[t] : 0;
    sm[t] = v;
    __syncthreads();
    for (int d = 1; d < 256; d <<= 1) {
        int x = (t >= d) ? sm[t - d] : 0;
        __syncthreads();
        sm[t] += x;
        __syncthreads();
    }
    g_bex[t] = sm[t] - v;   // exclusive
}

__global__ void k_scan_p3(int N) {
    __shared__ int sm[256];
    int t = threadIdx.x;
    int n = blockIdx.x * 256 + t;
    int v = (n < N) ? g_indeg[n] : 0;
    sm[t] = v;
    __syncthreads();
    for (int d = 1; d < 256; d <<= 1) {
        int x = (t >= d) ? sm[t - d] : 0;
        __syncthreads();
        sm[t] += x;
        __syncthreads();
    }
    int ex = sm[t] - v + g_bex[blockIdx.x];
    if (n < N) { g_off[n] = ex; g_cur[n] = ex; }
}

__global__ void k_fill(const int* __restrict__ ei, int E) {
    int e = blockIdx.x * blockDim.x + threadIdx.x;
    if (e < E) {
        int src = ei[e];
        int dst = ei[E + e];
        int p = atomicAdd(&g_cur[dst], 1);
        g_csr[p] = src;
    }
}

// ---------------- Wc = Wl @ W2, bpre = bl @ W2 ----------------
__global__ void k_wc(const float* __restrict__ Wl, const float* __restrict__ bl,
                     const float* __restrict__ W2) {
    int idx = blockIdx.x * blockDim.x + threadIdx.x;
    if (idx < F128 * F128) {
        int r = idx >> 7, c = idx & 127;
        float s = 0.0f;
        #pragma unroll 8
        for (int k = 0; k < F128; k++) s += Wl[r * F128 + k] * W2[k * F128 + c];
        g_Wc[idx] = s;
    }
    if (idx < F128) {
        float s = 0.0f;
        #pragma unroll 8
        for (int k = 0; k < F128; k++) s += bl[k] * W2[k * F128 + idx];
        g_bpre[idx] = s;
    }
}

// ---------------- GEMM 1: hs = (x @ W1) * dinv[row] ----------------
// Block: 256 threads, 64 rows x 128 cols tile, KT=32
__global__ void k_gemm1(const float* __restrict__ A, const float* __restrict__ B, int N) {
    __shared__ float As[64 * 32];
    __shared__ float Bs[32 * 128];
    int tid = threadIdx.x;
    int tc = tid & 31, tr = tid >> 5;
    int row0 = blockIdx.x * 64;
    float acc[8][4] = {};

    for (int k0 = 0; k0 < 128; k0 += 32) {
        // A tile: 64x32, each thread loads 2 float4 (row = tid>>2, cols (tid&3)*8)
        {
            int r = tid >> 2, c = (tid & 3) * 8;
            int gr = row0 + r;
            float4 v0 = make_float4(0, 0, 0, 0), v1 = make_float4(0, 0, 0, 0);
            if (gr < N) {
                v0 = *(const float4*)(A + gr * 128 + k0 + c);
                v1 = *(const float4*)(A + gr * 128 + k0 + c + 4);
            }
            *(float4*)(As + r * 32 + c) = v0;
            *(float4*)(As + r * 32 + c + 4) = v1;
        }
        // B tile: contiguous 4096 floats at B + k0*128
        {
            const float4* Bg = (const float4*)(B + k0 * 128);
            float4* Bs4 = (float4*)Bs;
            #pragma unroll
            for (int it = 0; it < 4; it++) Bs4[tid + 256 * it] = Bg[tid + 256 * it];
        }
        __syncthreads();
        #pragma unroll
        for (int k = 0; k < 32; k++) {
            float4 b = *(const float4*)(Bs + k * 128 + tc * 4);
            #pragma unroll
            for (int i = 0; i < 8; i++) {
                float a = As[(tr * 8 + i) * 32 + k];
                acc[i][0] += a * b.x; acc[i][1] += a * b.y;
                acc[i][2] += a * b.z; acc[i][3] += a * b.w;
            }
        }
        __syncthreads();
    }
    #pragma unroll
    for (int i = 0; i < 8; i++) {
        int r = row0 + tr * 8 + i;
        if (r < N) {
            float dv = g_dinv[r];
            float4 o = make_float4(acc[i][0] * dv, acc[i][1] * dv,
                                   acc[i][2] * dv, acc[i][3] * dv);
            *(float4*)(g_hs + r * 128 + tc * 4) = o;
        }
    }
}

// ---------------- GEMM 2: hs2 = (tanh(dinv*acc + b1) @ Wc + bpre) * dinv ----
__global__ void k_gemm2(const float* __restrict__ b1, int N) {
    __shared__ float As[64 * 32];
    __shared__ float Bs[32 * 128];
    int tid = threadIdx.x;
    int tc = tid & 31, tr = tid >> 5;
    int row0 = blockIdx.x * 64;
    float acc[8][4] = {};

    for (int k0 = 0; k0 < 128; k0 += 32) {
        {
            int r = tid >> 2, c = (tid & 3) * 8;
            int gr = row0 + r;
            float4 v0 = make_float4(0, 0, 0, 0), v1 = make_float4(0, 0, 0, 0);
            if (gr < N) {
                float dv = g_dinv[gr];
                float4 a0 = *(const float4*)(g_acc + gr * 128 + k0 + c);
                float4 a1 = *(const float4*)(g_acc + gr * 128 + k0 + c + 4);
                float4 q0 = *(const float4*)(b1 + k0 + c);
                float4 q1 = *(const float4*)(b1 + k0 + c + 4);
                v0 = make_float4(tanhf(dv * a0.x + q0.x), tanhf(dv * a0.y + q0.y),
                                 tanhf(dv * a0.z + q0.z), tanhf(dv * a0.w + q0.w));
                v1 = make_float4(tanhf(dv * a1.x + q1.x), tanhf(dv * a1.y + q1.y),
                                 tanhf(dv * a1.z + q1.z), tanhf(dv * a1.w + q1.w));
            }
            *(float4*)(As + r * 32 + c) = v0;
            *(float4*)(As + r * 32 + c + 4) = v1;
        }
        {
            const float4* Bg = (const float4*)(g_Wc + k0 * 128);
            float4* Bs4 = (float4*)Bs;
            #pragma unroll
            for (int it = 0; it < 4; it++) Bs4[tid + 256 * it] = Bg[tid + 256 * it];
        }
        __syncthreads();
        #pragma unroll
        for (int k = 0; k < 32; k++) {
            float4 b = *(const float4*)(Bs + k * 128 + tc * 4);
            #pragma unroll
            for (int i = 0; i < 8; i++) {
                float a = As[(tr * 8 + i) * 32 + k];
                acc[i][0] += a * b.x; acc[i][1] += a * b.y;
                acc[i][2] += a * b.z; acc[i][3] += a * b.w;
            }
        }
        __syncthreads();
    }
    float4 bp = *(const float4*)(g_bpre + tc * 4);
    #pragma unroll
    for (int i = 0; i < 8; i++) {
        int r = row0 + tr * 8 + i;
        if (r < N) {
            float dv = g_dinv[r];
            float4 o = make_float4((acc[i][0] + bp.x) * dv, (acc[i][1] + bp.y) * dv,
                                   (acc[i][2] + bp.z) * dv, (acc[i][3] + bp.w) * dv);
            *(float4*)(g_hs + r * 128 + tc * 4) = o;
        }
    }
}

// ---------------- Aggregation: acc[n] = hs[n] + sum_{in-edges} hs[src] -----
// one warp per node; lane handles float4 at col lane*4
__global__ void k_agg(int N) {
    int gw = (blockIdx.x * blockDim.x + threadIdx.x) >> 5;
    int lane = threadIdx.x & 31;
    if (gw >= N) return;
    const float4* hs4 = (const float4*)g_hs;
    float4* acc4 = (float4*)g_acc;
    int beg = g_off[gw];
    int cnt = g_indeg[gw];
    float4 s = hs4[gw * 32 + lane];  // self loop term (dinv factored out)
    int j = 0;
    for (; j + 4 <= cnt; j += 4) {
        int s0 = g_csr[beg + j];
        int s1 = g_csr[beg + j + 1];
        int s2 = g_csr[beg + j + 2];
        int s3 = g_csr[beg + j + 3];
        float4 a = hs4[s0 * 32 + lane];
        float4 b = hs4[s1 * 32 + lane];
        float4 c = hs4[s2 * 32 + lane];
        float4 d = hs4[s3 * 32 + lane];
        s = f4add(s, f4add(f4add(a, b), f4add(c, d)));
    }
    for (; j < cnt; j++) s = f4add(s, hs4[g_csr[beg + j] * 32 + lane]);
    acc4[gw * 32 + lane] = s;
}

// ---------------- Final: out = max_n( tanh(dinv*acc + b2) @ Wo + bo ) ------
// 64 rows x 64 cols tile, KT=32, 256 threads (8 rows x 2 cols per thread)
__global__ void k_final(const float* __restrict__ b2, const float* __restrict__ Wo,
                        const float* __restrict__ bo, float* __restrict__ out, int N) {
    __shared__ float As[64 * 32];
    __shared__ float Bs[32 * 64];
    int tid = threadIdx.x;
    int tc = tid & 31, tr = tid >> 5;
    int row0 = blockIdx.x * 64;
    float acc[8][2] = {};

    for (int k0 = 0; k0 < 128; k0 += 32) {
        {
            int r = tid >> 2, c = (tid & 3) * 8;
            int gr = row0 + r;
            float4 v0 = make_float4(0, 0, 0, 0), v1 = make_float4(0, 0, 0, 0);
            if (gr < N) {
                float dv = g_dinv[gr];
                float4 a0 = *(const float4*)(g_acc + gr * 128 + k0 + c);
                float4 a1 = *(const float4*)(g_acc + gr * 128 + k0 + c + 4);
                float4 q0 = *(const float4*)(b2 + k0 + c);
                float4 q1 = *(const float4*)(b2 + k0 + c + 4);
                v0 = make_float4(tanhf(dv * a0.x + q0.x), tanhf(dv * a0.y + q0.y),
                                 tanhf(dv * a0.z + q0.z), tanhf(dv * a0.w + q0.w));
                v1 = make_float4(tanhf(dv * a1.x + q1.x), tanhf(dv * a1.y + q1.y),
                                 tanhf(dv * a1.z + q1.z), tanhf(dv * a1.w + q1.w));
            }
            *(float4*)(As + r * 32 + c) = v0;
            *(float4*)(As + r * 32 + c + 4) = v1;
        }
        {
            // Wo tile rows k0..k0+32 x 64 cols: contiguous 2048 floats
            const float4* Bg = (const float4*)(Wo + k0 * 64);
            float4* Bs4 = (float4*)Bs;
            Bs4[tid] = Bg[tid];
            Bs4[tid + 256] = Bg[tid + 256];
        }
        __syncthreads();
        #pragma unroll
        for (int k = 0; k < 32; k++) {
            float2 b = *(const float2*)(Bs + k * 64 + tc * 2);
            #pragma unroll
            for (int i = 0; i < 8; i++) {
                float a = As[(tr * 8 + i) * 32 + k];
                acc[i][0] += a * b.x;
                acc[i][1] += a * b.y;
            }
        }
        __syncthreads();
    }
    float bo0 = bo[tc * 2], bo1 = bo[tc * 2 + 1];
    float m0 = -INFINITY, m1 = -INFINITY;
    #pragma unroll
    for (int i = 0; i < 8; i++) {
        int r = row0 + tr * 8 + i;
        if (r < N) {
            m0 = fmaxf(m0, acc[i][0] + bo0);
            m1 = fmaxf(m1, acc[i][1] + bo1);
        }
    }
    // cross-thread reduction over tr (8 rows of thread-maxima)
    As[tr * 64 + tc * 2] = m0;
    As[tr * 64 + tc * 2 + 1] = m1;
    __syncthreads();
    if (tid < 64) {
        float m = As[tid];
        #pragma unroll
        for (int j = 1; j < 8; j++) m = fmaxf(m, As[j * 64 + tid]);
        atomicMaxFloat(&out[tid], m);
    }
}

__global__ void k_init_out(float* out) {
    int t = threadIdx.x;
    if (t < 64) out[t] = -INFINITY;
}

// ---------------- launch ----------------
extern "C" void kernel_launch(void* const* d_in, const int* in_sizes, int n_in,
                              void* d_out, int out_size) {
    const float* x  = (const float*)d_in[0];
    const int*   ei = (const int*)d_in[1];
    const float* W1 = (const float*)d_in[2];
    const float* b1 = (const float*)d_in[3];
    const float* Wl = (const float*)d_in[4];
    const float* bl = (const float*)d_in[5];
    const float* W2 = (const float*)d_in[6];
    const float* b2 = (const float*)d_in[7];
    const float* Wo = (const float*)d_in[8];
    const float* bo = (const float*)d_in[9];
    float* out = (float*)d_out;

    int N = in_sizes[0] / F128;   // 50000
    int E = in_sizes[1] / 2;      // 800000

    int nbN = (N + 255) / 256;    // 196
    int nbE = (E + 255) / 256;

    k_init_indeg<<<nbN, 256>>>(N);
    k_count<<<nbE, 256>>>(ei, E);
    k_dinv<<<nbN, 256>>>(N);
    k_scan_p1<<<nbN, 256>>>(N);
    k_scan_p2<<<1, 256>>>(nbN);
    k_scan_p3<<<nbN, 256>>>(N);
    k_fill<<<nbE, 256>>>(ei, E);
    k_wc<<<(F128 * F128 + 255) / 256, 256>>>(Wl, bl, W2);

    int nbG = (N + 63) / 64;      // 782
    int nbA = (N + 7) / 8;        // 6250 (one warp per node, 8 warps/block)

    k_gemm1<<<nbG, 256>>>(x, W1, N);   // g_hs  = (x@W1)*dinv
    k_agg<<<nbA, 256>>>(N);            // g_acc = gather-sum
    k_gemm2<<<nbG, 256>>>(b1, N);      // g_hs  = (tanh(...)@Wc + bpre)*dinv
    k_agg<<<nbA, 256>>>(N);            // g_acc = gather-sum
    k_init_out<<<1, 64>>>(out);
    k_final<<<nbG, 256>>>(b2, Wo, bo, out, N);
}